// round 15
// baseline (speedup 1.0000x reference)
#include <cuda_runtime.h>
#include <cuda_bf16.h>
#include <math.h>
#include <stdint.h>

#define B_  32
#define S_  128
#define T_  64
#define E_  256
#define H_  512
#define V_  32000
#define GH  2048
#define DH  1024
#define DG  4096
#define TD  63
#define MROWS 2016
#define MPAD  2048

#if defined(__CUDA_ARCH_FEAT_SM103_ALL) || defined(__CUDA_ARCH_FEAT_SM100_ALL) || !defined(__CUDA_ARCH__)
#define HAS_TC 1
#else
#define HAS_TC 0
#endif

// ---------------- scratch ----------------
__device__ float g_pre_fT[(size_t)S_ * GH * B_];
__device__ float g_pre_bT[(size_t)S_ * GH * B_];
__device__ float g_dec_preT[(size_t)TD * DG * B_];
__device__ float g_enc_hT[2][2][H_ * B_];
__device__ float g_enc_cT[2][H_ * B_];
__device__ float g_dec_hT[2][DH * B_];
__device__ int   g_enc_rowidx[S_ * B_];
__device__ int   g_dec_rowidx[TD * B_];
__device__ __nv_bfloat16 g_Abig[(size_t)MPAD * 2048];   // [hi(1024) | lo(1024)]
__device__ __nv_bfloat16 g_Wbig[(size_t)V_ * 2048];     // [hi | lo]
__device__ __nv_bfloat16 g_Wp[(size_t)8192 * 512];      // Wf | Wb | Wd (split K=512)
__device__ __nv_bfloat16 g_Aenc[(size_t)4096 * 512];
__device__ __nv_bfloat16 g_Adec[(size_t)2048 * 512];
__device__ unsigned g_sync[192];

// ---------------- grid barrier ----------------
__device__ __forceinline__ void grid_barrier2(unsigned* cnt, unsigned* gen,
                                              unsigned step, unsigned nb)
{
    __syncthreads();
    if (threadIdx.x == 0) {
        __threadfence();
        unsigned old;
        asm volatile("atom.add.release.gpu.u32 %0, [%1], 1;"
                     : "=r"(old) : "l"(cnt) : "memory");
        if (old == step * nb - 1) {
            asm volatile("st.release.gpu.u32 [%0], %1;" :: "l"(gen), "r"(step) : "memory");
        } else {
            unsigned v;
            do {
                asm volatile("ld.acquire.gpu.u32 %0, [%1];" : "=r"(v) : "l"(gen) : "memory");
            } while (v < step);
        }
    }
    __syncthreads();
}

// ---------------- f32x2 helpers ----------------
__device__ __forceinline__ unsigned long long pk2(float lo, float hi)
{
    unsigned long long p;
    asm("mov.b64 %0, {%1, %2};" : "=l"(p) : "f"(lo), "f"(hi));
    return p;
}
__device__ __forceinline__ unsigned long long ffma2(unsigned long long a,
                                                    unsigned long long b,
                                                    unsigned long long c)
{
    unsigned long long d;
    asm("fma.rn.f32x2 %0, %1, %2, %3;" : "=l"(d) : "l"(a), "l"(b), "l"(c));
    return d;
}
__device__ __forceinline__ void unpk2(unsigned long long p, float& lo, float& hi)
{
    asm("mov.b64 {%0, %1}, %2;" : "=f"(lo), "=f"(hi) : "l"(p));
}

// ---------------- fast activations ----------------
__device__ __forceinline__ float fsig(float x)
{
    float e; asm("ex2.approx.f32 %0, %1;" : "=f"(e) : "f"(-1.4426950408889634f * x));
    float r; asm("rcp.approx.f32 %0, %1;" : "=f"(r) : "f"(1.f + e));
    return r;
}
__device__ __forceinline__ float ftanh(float x)
{
    float e; asm("ex2.approx.f32 %0, %1;" : "=f"(e) : "f"(2.8853900817779268f * x));
    float r; asm("rcp.approx.f32 %0, %1;" : "=f"(r) : "f"(1.f + e));
    return 1.f - 2.f * r;
}

// ---------------- prep ----------------
__global__ void prep_k(const int* __restrict__ src, const int* __restrict__ trg,
                       float* __restrict__ out)
{
    long idx = (long)blockIdx.x * blockDim.x + threadIdx.x;
    const long N0 = (long)B_ * V_;
    if (idx < N0) {
        long b = idx / V_, v = idx - b * V_;
        out[(size_t)b * T_ * V_ + v] = 0.f;
        return;
    }
    idx -= N0;
    if (idx < 2 * H_ * B_) { g_enc_hT[idx >> 14][0][idx & 16383] = 0.f; return; }
    idx -= 2 * H_ * B_;
    if (idx < S_ * B_) {
        int t = (int)(idx / B_), b = (int)(idx % B_);
        g_enc_rowidx[idx] = src[b * S_ + t];
        return;
    }
    idx -= S_ * B_;
    if (idx < TD * B_) {
        int t = (int)(idx / B_), b = (int)(idx % B_);
        g_dec_rowidx[idx] = trg[b * T_ + t];
        return;
    }
    idx -= TD * B_;
    if (idx < 192) { g_sync[idx] = 0; return; }
    idx -= 192;
    if (idx < (MPAD - MROWS) * 2048) {
        g_Abig[(size_t)(MROWS + (idx >> 11)) * 2048 + (idx & 2047)] = __float2bfloat16(0.f);
        return;
    }
}

// ---------------- split helper ----------------
__device__ __forceinline__ void split4(float4 v, __nv_bfloat16* hi, __nv_bfloat16* lo)
{
    hi[0] = __float2bfloat16(v.x); lo[0] = __float2bfloat16(v.x - __bfloat162float(hi[0]));
    hi[1] = __float2bfloat16(v.y); lo[1] = __float2bfloat16(v.y - __bfloat162float(hi[1]));
    hi[2] = __float2bfloat16(v.z); lo[2] = __float2bfloat16(v.z - __bfloat162float(hi[2]));
    hi[3] = __float2bfloat16(v.w); lo[3] = __float2bfloat16(v.w - __bfloat162float(hi[3]));
}

// ---------------- fused split conversions: fcW + Wih(x3) + gathered embeddings ----------
#define NW ((size_t)V_ * 256)
#define NP ((size_t)8192 * 64)
#define NA ((size_t)6144 * 64)
__global__ void conv_all_k(const float* __restrict__ fcW,
                           const float* __restrict__ Wf, const float* __restrict__ Wb,
                           const float* __restrict__ Wd,
                           const float* __restrict__ enc_emb,
                           const float* __restrict__ dec_emb)
{
    size_t i = (size_t)blockIdx.x * 256 + threadIdx.x;
    __nv_bfloat16 hi[4], lo[4];
    if (i < NW) {
        size_t n = i >> 8; int k4 = (int)(i & 255);
        float4 v = __ldcg((const float4*)fcW + i);
        split4(v, hi, lo);
        *(uint64_t*)(g_Wbig + n * 2048 + k4 * 4)        = *(uint64_t*)hi;
        *(uint64_t*)(g_Wbig + n * 2048 + 1024 + k4 * 4) = *(uint64_t*)lo;
        return;
    }
    i -= NW;
    if (i < NP) {
        size_t row = i >> 6; int k4 = (int)(i & 63);
        const float* src; size_t r = row;
        if (row < 2048)      src = Wf;
        else if (row < 4096) { src = Wb; r = row - 2048; }
        else                 { src = Wd; r = row - 4096; }
        float4 v = __ldcg((const float4*)(src + r * E_) + k4);
        split4(v, hi, lo);
        *(uint64_t*)(g_Wp + row * 512 + k4 * 4)       = *(uint64_t*)hi;
        *(uint64_t*)(g_Wp + row * 512 + 256 + k4 * 4) = *(uint64_t*)lo;
        return;
    }
    i -= NP;
    if (i < NA) {
        size_t row = i >> 6; int k4 = (int)(i & 63);
        __nv_bfloat16* dst;
        float4 v;
        if (row < 4096) {
            v = __ldcg((const float4*)(enc_emb + (size_t)g_enc_rowidx[row] * E_) + k4);
            dst = g_Aenc + row * 512;
        } else {
            size_t m = row - 4096;
            dst = g_Adec + m * 512;
            if (m < MROWS)
                v = __ldcg((const float4*)(dec_emb + (size_t)g_dec_rowidx[m] * E_) + k4);
            else
                v = make_float4(0.f, 0.f, 0.f, 0.f);
        }
        split4(v, hi, lo);
        *(uint64_t*)(dst + k4 * 4)       = *(uint64_t*)hi;
        *(uint64_t*)(dst + 256 + k4 * 4) = *(uint64_t*)lo;
    }
}

// ================= shared tcgen05 GEMM plumbing =================
#define STAGE  98304
#define OFF_AHI0 0
#define OFF_AHI1 16384
#define OFF_ALO0 32768
#define OFF_ALO1 49152
#define OFF_WHI  65536
#define OFF_WLO  81920
#define SMEM_HDR 1024
#define SMEM_TC  (SMEM_HDR + 2 * STAGE)
#define IDESC_F16 ((1u<<4)|(1u<<7)|(1u<<10)|((128u/8)<<17)|((128u/16)<<24))

static __device__ __forceinline__ uint32_t swz(uint32_t x) { return x ^ ((x >> 3) & 0x70); }

__device__ __forceinline__ uint32_t smem_u32(const void* p)
{
    uint32_t a;
    asm("{ .reg .u64 t; cvta.to.shared.u64 t, %1; cvt.u32.u64 %0, t; }" : "=r"(a) : "l"(p));
    return a;
}
__device__ __forceinline__ void cp16(uint32_t dst, const void* src)
{
    asm volatile("cp.async.cg.shared.global [%0], [%1], 16;" :: "r"(dst), "l"(src));
}

#if HAS_TC
__device__ __forceinline__ uint32_t elect1()
{
    uint32_t p;
    asm volatile("{ .reg .pred p; elect.sync _|p, 0xFFFFFFFF; selp.b32 %0, 1, 0, p; }" : "=r"(p));
    return p;
}
__device__ __forceinline__ void mma_f16_ss(uint32_t d, uint64_t ad, uint64_t bd,
                                           uint32_t idesc, uint32_t en)
{
    asm volatile(
        "{\n\t.reg .pred p;\n\tsetp.ne.u32 p, %5, 0;\n\t"
        "tcgen05.mma.cta_group::1.kind::f16 [%0], %1, %2, %3, {%4,%4,%4,%4}, p;\n\t}"
        :: "r"(d), "l"(ad), "l"(bd), "r"(idesc), "r"(0u), "r"(en) : "memory");
}

// coalesced chunk loader (R14-proven)
template <int RS, int LOFF>
__device__ __forceinline__ void load_chunk_g(const __nv_bfloat16* Ag, const __nv_bfloat16* Wg,
                                             int kc, uint32_t sbase, int tid)
{
#pragma unroll
    for (int g = 0; g < 8; g++) {
        int idx = g * 256 + tid;
        int row = idx >> 3, c = idx & 7;
        uint32_t hb = (row < 128) ? OFF_AHI0 : OFF_AHI1;
        uint32_t lb = (row < 128) ? OFF_ALO0 : OFF_ALO1;
        uint32_t so = swz((uint32_t)(row & 127) * 128 + c * 16);
        const __nv_bfloat16* srow = Ag + (size_t)row * RS + kc + c * 8;
        cp16(sbase + hb + so, srow);
        cp16(sbase + lb + so, srow + LOFF);
    }
#pragma unroll
    for (int g = 0; g < 4; g++) {
        int idx = g * 256 + tid;
        int row = idx >> 3, c = idx & 7;
        uint32_t so = swz((uint32_t)row * 128 + c * 16);
        const __nv_bfloat16* srow = Wg + (size_t)row * RS + kc + c * 8;
        cp16(sbase + OFF_WHI + so, srow);
        cp16(sbase + OFF_WLO + so, srow + LOFF);
    }
    asm volatile("cp.async.commit_group;" ::: "memory");
}

template <int RS, int LOFF, int KCHN>
__device__ __forceinline__ uint32_t tc_mainloop(const __nv_bfloat16* Ag,
                                                const __nv_bfloat16* Wg,
                                                uint32_t sbase, int tid, int wid)
{
    if (wid == 0)
        asm volatile("tcgen05.alloc.cta_group::1.sync.aligned.shared::cta.b32 [%0], 512;"
                     :: "r"(sbase) : "memory");
    if (tid == 0) {
        asm volatile("mbarrier.init.shared.b64 [%0], 1;" :: "r"(sbase + 16) : "memory");
        asm volatile("mbarrier.init.shared.b64 [%0], 1;" :: "r"(sbase + 24) : "memory");
    }
    __syncthreads();
    uint32_t tmem;
    asm volatile("ld.shared.b32 %0, [%1];" : "=r"(tmem) : "r"(sbase));

    load_chunk_g<RS, LOFF>(Ag, Wg, 0, sbase + SMEM_HDR, tid);
    if (KCHN > 1) load_chunk_g<RS, LOFF>(Ag, Wg, 64, sbase + SMEM_HDR + STAGE, tid);

    int phase0 = 0, phase1 = 0;
    for (int c = 0; c < KCHN; c++) {
        const int p = c & 1;
        if (c + 1 < KCHN) asm volatile("cp.async.wait_group 1;" ::: "memory");
        else              asm volatile("cp.async.wait_group 0;" ::: "memory");
        __syncthreads();
        asm volatile("fence.proxy.async.shared::cta;" ::: "memory");

        if (wid == 0 && elect1()) {
            const uint32_t st = sbase + SMEM_HDR + p * STAGE;
            const uint64_t BASE = (uint64_t(2) << 61) | (uint64_t(1) << 46) |
                                  (uint64_t(64) << 32) | (uint64_t(1) << 16);
            uint64_t dAhi0 = BASE | (((st + OFF_AHI0) >> 4) & 0x3FFF);
            uint64_t dAhi1 = BASE | (((st + OFF_AHI1) >> 4) & 0x3FFF);
            uint64_t dAlo0 = BASE | (((st + OFF_ALO0) >> 4) & 0x3FFF);
            uint64_t dAlo1 = BASE | (((st + OFF_ALO1) >> 4) & 0x3FFF);
            uint64_t dWhi  = BASE | (((st + OFF_WHI) >> 4) & 0x3FFF);
            uint64_t dWlo  = BASE | (((st + OFF_WLO) >> 4) & 0x3FFF);
#pragma unroll
            for (int ks = 0; ks < 4; ks++) {
                uint32_t en0 = (c == 0 && ks == 0) ? 0u : 1u;
                mma_f16_ss(tmem + 0,   dAhi0 + ks * 2, dWhi + ks * 2, IDESC_F16, en0);
                mma_f16_ss(tmem + 128, dAhi1 + ks * 2, dWhi + ks * 2, IDESC_F16, en0);
                mma_f16_ss(tmem + 0,   dAhi0 + ks * 2, dWlo + ks * 2, IDESC_F16, 1u);
                mma_f16_ss(tmem + 128, dAhi1 + ks * 2, dWlo + ks * 2, IDESC_F16, 1u);
                mma_f16_ss(tmem + 0,   dAlo0 + ks * 2, dWhi + ks * 2, IDESC_F16, 1u);
                mma_f16_ss(tmem + 128, dAlo1 + ks * 2, dWhi + ks * 2, IDESC_F16, 1u);
            }
            asm volatile(
                "tcgen05.commit.cta_group::1.mbarrier::arrive::one.shared::cluster.b64 [%0];"
                :: "r"(sbase + 16 + p * 8) : "memory");
        }
        {
            uint32_t mb = sbase + 16 + p * 8;
            uint32_t ph = p ? phase1 : phase0;
            uint32_t done;
            do {
                asm volatile(
                    "{\n\t.reg .pred q;\n\t"
                    "mbarrier.try_wait.parity.shared.b64 q, [%1], %2, 0x989680;\n\t"
                    "selp.b32 %0, 1, 0, q;\n\t}"
                    : "=r"(done) : "r"(mb), "r"(ph) : "memory");
            } while (!done);
            if (p) phase1 ^= 1; else phase0 ^= 1;
        }
        if (c + 2 < KCHN)
            load_chunk_g<RS, LOFF>(Ag, Wg, (c + 2) * 64, sbase + SMEM_HDR + p * STAGE, tid);
    }
    asm volatile("tcgen05.fence::after_thread_sync;" ::: "memory");
    return tmem;
}

#define LDTM32(r, addr) \
    asm volatile( \
        "tcgen05.ld.sync.aligned.32x32b.x32.b32 " \
        "{%0,%1,%2,%3,%4,%5,%6,%7,%8,%9,%10,%11,%12,%13,%14,%15," \
        "%16,%17,%18,%19,%20,%21,%22,%23,%24,%25,%26,%27,%28,%29,%30,%31}, [%32];" \
        : "=r"((r)[0]), "=r"((r)[1]), "=r"((r)[2]), "=r"((r)[3]), "=r"((r)[4]), "=r"((r)[5]), \
          "=r"((r)[6]), "=r"((r)[7]), "=r"((r)[8]), "=r"((r)[9]), "=r"((r)[10]), "=r"((r)[11]), \
          "=r"((r)[12]), "=r"((r)[13]), "=r"((r)[14]), "=r"((r)[15]), "=r"((r)[16]), "=r"((r)[17]), \
          "=r"((r)[18]), "=r"((r)[19]), "=r"((r)[20]), "=r"((r)[21]), "=r"((r)[22]), "=r"((r)[23]), \
          "=r"((r)[24]), "=r"((r)[25]), "=r"((r)[26]), "=r"((r)[27]), "=r"((r)[28]), "=r"((r)[29]), \
          "=r"((r)[30]), "=r"((r)[31]) \
        : "r"(addr))
#endif  // HAS_TC

// ---------------- fused pregate GEMMs (z selects problem) ----------------
__global__ __launch_bounds__(256, 1)
void pgemm3_tc(const float* __restrict__ eb_f, const float* __restrict__ eb_b,
               const float* __restrict__ db)
{
#if HAS_TC
    const int z = blockIdx.z;
    const __nv_bfloat16 *A, *W;
    const float* bias;
    float* C;
    int Ntot, Mvalid;
    if (z == 0) {
        if (blockIdx.x >= 16 || blockIdx.y >= 16) return;
        A = g_Aenc; W = g_Wp; bias = eb_f; C = g_pre_fT; Ntot = GH; Mvalid = 4096;
    } else if (z == 1) {
        if (blockIdx.x >= 16 || blockIdx.y >= 16) return;
        A = g_Aenc; W = g_Wp + (size_t)2048 * 512; bias = eb_b; C = g_pre_bT; Ntot = GH; Mvalid = 4096;
    } else {
        if (blockIdx.y >= 8) return;
        A = g_Adec; W = g_Wp + (size_t)4096 * 512; bias = db; C = g_dec_preT; Ntot = DG; Mvalid = MROWS;
    }
    extern __shared__ __align__(1024) unsigned char sm[];
    const uint32_t sbase = smem_u32(sm);
    const int tid = threadIdx.x, wid = tid >> 5, lane = tid & 31;
    const int n0 = blockIdx.x * 128;
    const int m0g = blockIdx.y * 256;
    const __nv_bfloat16* Ag = A + (size_t)m0g * 512;
    const __nv_bfloat16* Wg = W + (size_t)n0 * 512;

    uint32_t tmem = tc_mainloop<512, 256, 4>(Ag, Wg, sbase, tid, wid);

    {
        const int sub = tid >> 7;
        const int wiw = (tid >> 5) & 3;
        const int mrow = m0g + sub * 128 + wiw * 32 + lane;
        const uint32_t warp_off = ((uint32_t)(tid & 127) >> 5) << 21;
        const uint32_t dbase = tmem + sub * 128 + warp_off;
        const bool valid = mrow < Mvalid;
        const int t = mrow >> 5, b = mrow & 31;
#pragma unroll
        for (int q = 0; q < 4; q++) {
            uint32_t r[32];
            LDTM32(r, dbase + q * 32);
            asm volatile("tcgen05.wait::ld.sync.aligned;" ::: "memory");
            if (valid) {
#pragma unroll
                for (int c1 = 0; c1 < 32; c1++) {
                    const int n = n0 + q * 32 + c1;
                    C[((size_t)t * Ntot + n) * B_ + b] = __uint_as_float(r[c1]) + bias[n];
                }
            }
        }
    }
    __syncthreads();
    if (wid == 0) {
        asm volatile("tcgen05.relinquish_alloc_permit.cta_group::1.sync.aligned;" ::: "memory");
        asm volatile("tcgen05.dealloc.cta_group::1.sync.aligned.b32 %0, 512;" :: "r"(tmem));
    }
#endif
}

// ---------------- fused persistent recurrence (encoder then decoder) ----------------
// smem layout (192KB total):
//   enc phase: sw_if [0,32KB) | sw_go [32,64KB) | shT [64,128KB)
//   dec phase: sw_if [0,64KB) | sw_go [64,128KB) | shH [128,192KB)
__global__ void rec_persist_k(const float* __restrict__ Whh_f,
                              const float* __restrict__ Whh_b,
                              const float* __restrict__ dWhh)
{
    extern __shared__ float smemf[];
    const int w = threadIdx.x >> 5, lane = threadIdx.x & 31;

    // ======== encoder phase ========
    {
        float2* sw_if = (float2*)smemf;
        float2* sw_go = (float2*)(smemf + 8192);
        float*  shT   = smemf + 16384;
        const int dir = blockIdx.x >> 6, cb = blockIdx.x & 63;
        const int j = cb * 8 + w;
        const float* Whh = dir ? Whh_b : Whh_f;
        const float* preBase = dir ? g_pre_bT : g_pre_fT;
        unsigned* cnt = &g_sync[dir * 64];
        unsigned* gen = &g_sync[dir * 64 + 32];

        {
            const int base_j = cb * 8;
            for (int idx = threadIdx.x; idx < 8 * H_; idx += 256) {
                int c = idx >> 9, k = idx & 511;
                float wi = Whh[(size_t)(0 * H_ + base_j + c) * H_ + k];
                float wf = Whh[(size_t)(1 * H_ + base_j + c) * H_ + k];
                float wg = Whh[(size_t)(2 * H_ + base_j + c) * H_ + k];
                float wo = Whh[(size_t)(3 * H_ + base_j + c) * H_ + k];
                sw_if[idx] = make_float2(wi, wf);
                sw_go[idx] = make_float2(wg, wo);
            }
        }
        __syncthreads();

        const ulonglong2* pif = (const ulonglong2*)(sw_if + (size_t)w * H_);
        const ulonglong2* pgo = (const ulonglong2*)(sw_go + (size_t)w * H_);
        float cst = 0.f;

        for (int s = 0; s < S_; s++) {
            const float4* s4 = (const float4*)g_enc_hT[dir][s & 1];
            float4* d4 = (float4*)shT;
            for (int i = threadIdx.x; i < H_ * B_ / 4; i += 256) d4[i] = __ldcg(s4 + i);
            __syncthreads();
            const int t = dir ? (S_ - 1 - s) : s;
            const float* preT = preBase + (size_t)t * GH * B_;
            unsigned long long acc_if = pk2(__ldcg(preT + (size_t)(0 * H_ + j) * B_ + lane),
                                            __ldcg(preT + (size_t)(1 * H_ + j) * B_ + lane));
            unsigned long long acc_go = pk2(__ldcg(preT + (size_t)(2 * H_ + j) * B_ + lane),
                                            __ldcg(preT + (size_t)(3 * H_ + j) * B_ + lane));
#pragma unroll 4
            for (int k4 = 0; k4 < H_ / 4; k4++) {
                ulonglong2 a01 = pif[k4 * 2], a23 = pif[k4 * 2 + 1];
                ulonglong2 g01 = pgo[k4 * 2], g23 = pgo[k4 * 2 + 1];
                float h0 = shT[(k4 * 4 + 0) * B_ + lane];
                float h1 = shT[(k4 * 4 + 1) * B_ + lane];
                float h2 = shT[(k4 * 4 + 2) * B_ + lane];
                float h3 = shT[(k4 * 4 + 3) * B_ + lane];
                unsigned long long H0 = pk2(h0, h0), H1 = pk2(h1, h1);
                unsigned long long H2 = pk2(h2, h2), H3 = pk2(h3, h3);
                acc_if = ffma2(a01.x, H0, acc_if);
                acc_if = ffma2(a01.y, H1, acc_if);
                acc_if = ffma2(a23.x, H2, acc_if);
                acc_if = ffma2(a23.y, H3, acc_if);
                acc_go = ffma2(g01.x, H0, acc_go);
                acc_go = ffma2(g01.y, H1, acc_go);
                acc_go = ffma2(g23.x, H2, acc_go);
                acc_go = ffma2(g23.y, H3, acc_go);
            }
            float ai, af, ag, ao;
            unpk2(acc_if, ai, af);
            unpk2(acc_go, ag, ao);
            float iv = fsig(ai), fv = fsig(af), gv = ftanh(ag), ov = fsig(ao);
            cst = fv * cst + iv * gv;
            __stcg(&g_enc_hT[dir][(s + 1) & 1][(size_t)j * B_ + lane], ov * ftanh(cst));
            if (s == S_ - 1) __stcg(&g_enc_cT[dir][(size_t)j * B_ + lane], cst);
            grid_barrier2(cnt, gen, (unsigned)(s + 1), 64u);
        }
    }

    // ======== stage decoder weights (local; enc compute done) ========
    {
        float2* sw_if = (float2*)smemf;
        float2* sw_go = (float2*)(smemf + 16384);
        const int base_j = blockIdx.x * 8;
        for (int idx = threadIdx.x; idx < 8 * DH; idx += 256) {
            int c = idx >> 10, k = idx & 1023;
            float wi = dWhh[(size_t)(0 * DH + base_j + c) * DH + k];
            float wf = dWhh[(size_t)(1 * DH + base_j + c) * DH + k];
            float wg = dWhh[(size_t)(2 * DH + base_j + c) * DH + k];
            float wo = dWhh[(size_t)(3 * DH + base_j + c) * DH + k];
            sw_if[idx] = make_float2(wi, wf);
            sw_go[idx] = make_float2(wg, wo);
        }
    }

    // transition: all 128 blocks (both dirs) complete
    unsigned* cnt = &g_sync[128];
    unsigned* gen = &g_sync[160];
    grid_barrier2(cnt, gen, 1u, 128u);

    // ======== decoder phase ========
    {
        float2* sw_if = (float2*)smemf;
        float2* sw_go = (float2*)(smemf + 16384);
        float*  shH   = smemf + 32768;
        const int j = blockIdx.x * 8 + w;

        float cst, h0v;
        if (j < H_) {
            cst = __ldcg(&g_enc_cT[0][j * B_ + lane]);
            h0v = __ldcg(&g_enc_hT[0][0][j * B_ + lane]);
        } else {
            cst = __ldcg(&g_enc_cT[1][(j - H_) * B_ + lane]);
            h0v = __ldcg(&g_enc_hT[1][0][(j - H_) * B_ + lane]);
        }
        __stcg(&g_dec_hT[0][(size_t)j * B_ + lane], h0v);
        grid_barrier2(cnt, gen, 2u, 128u);

        for (int t = 0; t < TD; t++) {
            const float* preT = g_dec_preT + (size_t)t * DG * B_;
            unsigned long long acc_if = pk2(__ldcg(preT + (size_t)(0 * DH + j) * B_ + lane),
                                            __ldcg(preT + (size_t)(1 * DH + j) * B_ + lane));
            unsigned long long acc_go = pk2(__ldcg(preT + (size_t)(2 * DH + j) * B_ + lane),
                                            __ldcg(preT + (size_t)(3 * DH + j) * B_ + lane));

#pragma unroll
            for (int half = 0; half < 2; half++) {
                const float4* s4 = (const float4*)g_dec_hT[t & 1] + half * 4096;
                float4* d4 = (float4*)shH;
                for (int i = threadIdx.x; i < 4096; i += 256) d4[i] = __ldcg(s4 + i);
                __syncthreads();
                const ulonglong2* pif =
                    (const ulonglong2*)(sw_if + (size_t)w * DH) + half * 256;
                const ulonglong2* pgo =
                    (const ulonglong2*)(sw_go + (size_t)w * DH) + half * 256;
#pragma unroll 4
                for (int k4 = 0; k4 < 128; k4++) {
                    ulonglong2 a01 = pif[k4 * 2], a23 = pif[k4 * 2 + 1];
                    ulonglong2 g01 = pgo[k4 * 2], g23 = pgo[k4 * 2 + 1];
                    float h0 = shH[(k4 * 4 + 0) * B_ + lane];
                    float h1 = shH[(k4 * 4 + 1) * B_ + lane];
                    float h2 = shH[(k4 * 4 + 2) * B_ + lane];
                    float h3 = shH[(k4 * 4 + 3) * B_ + lane];
                    unsigned long long H0 = pk2(h0, h0), H1 = pk2(h1, h1);
                    unsigned long long H2 = pk2(h2, h2), H3 = pk2(h3, h3);
                    acc_if = ffma2(a01.x, H0, acc_if);
                    acc_if = ffma2(a01.y, H1, acc_if);
                    acc_if = ffma2(a23.x, H2, acc_if);
                    acc_if = ffma2(a23.y, H3, acc_if);
                    acc_go = ffma2(g01.x, H0, acc_go);
                    acc_go = ffma2(g01.y, H1, acc_go);
                    acc_go = ffma2(g23.x, H2, acc_go);
                    acc_go = ffma2(g23.y, H3, acc_go);
                }
                if (half == 0) __syncthreads();
            }

            float ai, af, ag, ao;
            unpk2(acc_if, ai, af);
            unpk2(acc_go, ag, ao);
            float iv = fsig(ai), fv = fsig(af), gv = ftanh(ag), ov = fsig(ao);
            cst = fv * cst + iv * gv;
            float hv = ov * ftanh(cst);
            __stcg(&g_dec_hT[(t + 1) & 1][(size_t)j * B_ + lane], hv);
            size_t m = (size_t)t * B_ + lane;
            __nv_bfloat16 hi = __float2bfloat16(hv);
            g_Abig[m * 2048 + j] = hi;
            g_Abig[m * 2048 + 1024 + j] = __float2bfloat16(hv - __bfloat162float(hi));
            grid_barrier2(cnt, gen, (unsigned)(t + 3), 128u);
        }
    }
}

// ---------------- final logits GEMM ----------------
__global__ __launch_bounds__(256, 1)
void bgemm_tc(const float* __restrict__ bias, float* __restrict__ out)
{
#if HAS_TC
    extern __shared__ __align__(1024) unsigned char sm[];
    const uint32_t sbase = smem_u32(sm);
    const int tid = threadIdx.x, wid = tid >> 5, lane = tid & 31;
    const int n0 = blockIdx.x * 128;
    const int m0g = blockIdx.y * 256;
    const __nv_bfloat16* Ag = g_Abig + (size_t)m0g * 2048;
    const __nv_bfloat16* Wg = g_Wbig + (size_t)n0 * 2048;

    uint32_t tmem = tc_mainloop<2048, 1024, 16>(Ag, Wg, sbase, tid, wid);

    {
        const int sub = tid >> 7;
        const int wiw = (tid >> 5) & 3;
        const int mrow = m0g + sub * 128 + wiw * 32 + lane;
        const uint32_t warp_off = ((uint32_t)(tid & 127) >> 5) << 21;
        const uint32_t dbase = tmem + sub * 128 + warp_off;
        const bool valid = mrow < MROWS;
        const int t = mrow >> 5, b = mrow & 31;
        float* orow = out + (size_t)(b * T_ + t + 1) * V_ + n0;
#pragma unroll
        for (int q = 0; q < 4; q++) {
            uint32_t r[32];
            LDTM32(r, dbase + q * 32);
            asm volatile("tcgen05.wait::ld.sync.aligned;" ::: "memory");
            if (valid) {
#pragma unroll
                for (int c4 = 0; c4 < 8; c4++) {
                    const int n = q * 32 + c4 * 4;
                    float4 bb = *(const float4*)(bias + n0 + n);
                    float4 v;
                    v.x = __uint_as_float(r[c4 * 4 + 0]) + bb.x;
                    v.y = __uint_as_float(r[c4 * 4 + 1]) + bb.y;
                    v.z = __uint_as_float(r[c4 * 4 + 2]) + bb.z;
                    v.w = __uint_as_float(r[c4 * 4 + 3]) + bb.w;
                    *(float4*)(orow + n) = v;
                }
            }
        }
    }
    __syncthreads();
    if (wid == 0) {
        asm volatile("tcgen05.relinquish_alloc_permit.cta_group::1.sync.aligned;" ::: "memory");
        asm volatile("tcgen05.dealloc.cta_group::1.sync.aligned.b32 %0, 512;" :: "r"(tmem));
    }
#endif
}

// ---------------- launch ----------------
extern "C" void kernel_launch(void* const* d_in, const int* in_sizes, int n_in,
                              void* d_out, int out_size)
{
    (void)in_sizes; (void)n_in; (void)out_size;
    const int*   src     = (const int*)d_in[0];
    const int*   trg     = (const int*)d_in[1];
    const float* enc_emb = (const float*)d_in[2];
    const float* dec_emb = (const float*)d_in[3];
    const float* eWih_f  = (const float*)d_in[4];
    const float* eWhh_f  = (const float*)d_in[5];
    const float* eb_f    = (const float*)d_in[6];
    const float* eWih_b  = (const float*)d_in[7];
    const float* eWhh_b  = (const float*)d_in[8];
    const float* eb_b    = (const float*)d_in[9];
    const float* dWih    = (const float*)d_in[10];
    const float* dWhh    = (const float*)d_in[11];
    const float* db      = (const float*)d_in[12];
    const float* fcW     = (const float*)d_in[13];
    const float* fcb     = (const float*)d_in[14];
    float* out = (float*)d_out;

    cudaFuncSetAttribute(rec_persist_k, cudaFuncAttributeMaxDynamicSharedMemorySize, 196608);
    cudaFuncSetAttribute(bgemm_tc, cudaFuncAttributeMaxDynamicSharedMemorySize, SMEM_TC);
    cudaFuncSetAttribute(pgemm3_tc, cudaFuncAttributeMaxDynamicSharedMemorySize, SMEM_TC);

    long total = (long)B_ * V_ + 2L * H_ * B_ + (long)S_ * B_ + (long)TD * B_
               + 192 + (long)(MPAD - MROWS) * 2048;
    prep_k<<<(unsigned)((total + 255) / 256), 256>>>(src, trg, out);

    size_t conv_total = NW + NP + NA;
    conv_all_k<<<(unsigned)((conv_total + 255) / 256), 256>>>(
        fcW, eWih_f, eWih_b, dWih, enc_emb, dec_emb);

    pgemm3_tc<<<dim3(32, 16, 3), 256, SMEM_TC>>>(eb_f, eb_b, db);

    rec_persist_k<<<128, 256, 196608>>>(eWhh_f, eWhh_b, dWhh);

    bgemm_tc<<<dim3(V_ / 128, MPAD / 256), 256, SMEM_TC>>>(fcb, out);
}

// round 17
// speedup vs baseline: 1.0926x; 1.0926x over previous
#include <cuda_runtime.h>
#include <cuda_bf16.h>
#include <math.h>
#include <stdint.h>

#define B_  32
#define S_  128
#define T_  64
#define E_  256
#define H_  512
#define V_  32000
#define GH  2048
#define DH  1024
#define DG  4096
#define TD  63
#define MROWS 2016
#define MPAD  2048

#if defined(__CUDA_ARCH_FEAT_SM103_ALL) || defined(__CUDA_ARCH_FEAT_SM100_ALL) || !defined(__CUDA_ARCH__)
#define HAS_TC 1
#else
#define HAS_TC 0
#endif

// ---------------- scratch ----------------
// GEMM operands stored PRE-SWIZZLED (SW128) in chunk-tiled blocks that are
// byte-exact images of the smem stage, so cp.async.bulk + the R14-proven
// SW128 descriptor reproduce R14's math bit-for-bit.
//  A block/chunk (64KB): [AHI0 16KB | AHI1 | ALO0 | ALO1], 128 rows x 128B each
//  W block/chunk (32KB): [WHI 16KB | WLO]
__device__ float g_pre_fT[(size_t)S_ * GH * B_];
__device__ float g_pre_bT[(size_t)S_ * GH * B_];
__device__ float g_dec_preT[(size_t)TD * DG * B_];
__device__ float g_enc_hT[2][2][H_ * B_];
__device__ float g_enc_cT[2][H_ * B_];
__device__ float g_dec_hT[2][DH * B_];
__device__ int   g_enc_rowidx[S_ * B_];
__device__ int   g_dec_rowidx[TD * B_];
__device__ __nv_bfloat16 g_Abig[(size_t)MPAD * 2048];   // 8 tiles x 16 chunks x 64KB
__device__ __nv_bfloat16 g_Wbig[(size_t)V_ * 2048];     // 250 tiles x 16 chunks x 32KB
__device__ __nv_bfloat16 g_Wp[(size_t)8192 * 512];      // 64 tiles x 4 chunks x 32KB
__device__ __nv_bfloat16 g_Aenc[(size_t)4096 * 512];    // 16 tiles x 4 chunks x 64KB
__device__ __nv_bfloat16 g_Adec[(size_t)2048 * 512];    // 8 tiles x 4 chunks x 64KB
__device__ unsigned g_sync[192];

static __device__ __forceinline__ uint32_t swz(uint32_t x) { return x ^ ((x >> 3) & 0x70); }

// ---------------- tiled+swizzled element-index helpers (hi; lo at +off) ----------------
__device__ __forceinline__ size_t a_big_elem(int m, int j)   // lo = +16384
{
    uint32_t inner = swz((uint32_t)(m & 127) * 128 + (uint32_t)(j & 63) * 2);
    return (((size_t)(m >> 8) * 1048576) + ((size_t)(j >> 6) * 65536) +
            (size_t)(((m >> 7) & 1) * 16384) + inner) >> 1;
}
__device__ __forceinline__ size_t w_big_elem(int n, int k)   // lo = +8192
{
    uint32_t inner = swz((uint32_t)(n & 127) * 128 + (uint32_t)(k & 63) * 2);
    return (((size_t)(n >> 7) * 524288) + ((size_t)(k >> 6) * 32768) + inner) >> 1;
}
__device__ __forceinline__ size_t a_pre_elem(int m, int k)   // lo = +16384
{
    uint32_t inner = swz((uint32_t)(m & 127) * 128 + (uint32_t)(k & 63) * 2);
    return (((size_t)(m >> 8) * 262144) + ((size_t)(k >> 6) * 65536) +
            (size_t)(((m >> 7) & 1) * 16384) + inner) >> 1;
}
__device__ __forceinline__ size_t w_pre_elem(int r, int k)   // lo = +8192
{
    uint32_t inner = swz((uint32_t)(r & 127) * 128 + (uint32_t)(k & 63) * 2);
    return (((size_t)(r >> 7) * 131072) + ((size_t)(k >> 6) * 32768) + inner) >> 1;
}

// ---------------- grid barrier ----------------
__device__ __forceinline__ void grid_barrier2(unsigned* cnt, unsigned* gen,
                                              unsigned step, unsigned nb)
{
    __syncthreads();
    if (threadIdx.x == 0) {
        __threadfence();
        unsigned old;
        asm volatile("atom.add.release.gpu.u32 %0, [%1], 1;"
                     : "=r"(old) : "l"(cnt) : "memory");
        if (old == step * nb - 1) {
            asm volatile("st.release.gpu.u32 [%0], %1;" :: "l"(gen), "r"(step) : "memory");
        } else {
            unsigned v;
            do {
                asm volatile("ld.acquire.gpu.u32 %0, [%1];" : "=r"(v) : "l"(gen) : "memory");
            } while (v < step);
        }
    }
    __syncthreads();
}

// ---------------- f32x2 helpers ----------------
__device__ __forceinline__ unsigned long long pk2(float lo, float hi)
{
    unsigned long long p;
    asm("mov.b64 %0, {%1, %2};" : "=l"(p) : "f"(lo), "f"(hi));
    return p;
}
__device__ __forceinline__ unsigned long long ffma2(unsigned long long a,
                                                    unsigned long long b,
                                                    unsigned long long c)
{
    unsigned long long d;
    asm("fma.rn.f32x2 %0, %1, %2, %3;" : "=l"(d) : "l"(a), "l"(b), "l"(c));
    return d;
}
__device__ __forceinline__ void unpk2(unsigned long long p, float& lo, float& hi)
{
    asm("mov.b64 {%0, %1}, %2;" : "=f"(lo), "=f"(hi) : "l"(p));
}

// ---------------- fast activations ----------------
__device__ __forceinline__ float fsig(float x)
{
    float e; asm("ex2.approx.f32 %0, %1;" : "=f"(e) : "f"(-1.4426950408889634f * x));
    float r; asm("rcp.approx.f32 %0, %1;" : "=f"(r) : "f"(1.f + e));
    return r;
}
__device__ __forceinline__ float ftanh(float x)
{
    float e; asm("ex2.approx.f32 %0, %1;" : "=f"(e) : "f"(2.8853900817779268f * x));
    float r; asm("rcp.approx.f32 %0, %1;" : "=f"(r) : "f"(1.f + e));
    return 1.f - 2.f * r;
}

// ---------------- prep ----------------
__global__ void prep_k(const int* __restrict__ src, const int* __restrict__ trg,
                       float* __restrict__ out)
{
    long idx = (long)blockIdx.x * blockDim.x + threadIdx.x;
    const long N0 = (long)B_ * V_;
    if (idx < N0) {
        long b = idx / V_, v = idx - b * V_;
        out[(size_t)b * T_ * V_ + v] = 0.f;
        return;
    }
    idx -= N0;
    if (idx < 2 * H_ * B_) { g_enc_hT[idx >> 14][0][idx & 16383] = 0.f; return; }
    idx -= 2 * H_ * B_;
    if (idx < S_ * B_) {
        int t = (int)(idx / B_), b = (int)(idx % B_);
        g_enc_rowidx[idx] = src[b * S_ + t];
        return;
    }
    idx -= S_ * B_;
    if (idx < TD * B_) {
        int t = (int)(idx / B_), b = (int)(idx % B_);
        g_dec_rowidx[idx] = trg[b * T_ + t];
        return;
    }
    idx -= TD * B_;
    if (idx < 192) { g_sync[idx] = 0; return; }
    idx -= 192;
    if (idx < (MPAD - MROWS) * 2048) {
        int m = MROWS + (int)(idx >> 11), col = (int)(idx & 2047);
        size_t a;
        if (col < 1024) a = a_big_elem(m, col);
        else            a = a_big_elem(m, col - 1024) + 16384;
        g_Abig[a] = __float2bfloat16(0.f);
        return;
    }
}

// ---------------- split helper ----------------
__device__ __forceinline__ void split4(float4 v, __nv_bfloat16* hi, __nv_bfloat16* lo)
{
    hi[0] = __float2bfloat16(v.x); lo[0] = __float2bfloat16(v.x - __bfloat162float(hi[0]));
    hi[1] = __float2bfloat16(v.y); lo[1] = __float2bfloat16(v.y - __bfloat162float(hi[1]));
    hi[2] = __float2bfloat16(v.z); lo[2] = __float2bfloat16(v.z - __bfloat162float(hi[2]));
    hi[3] = __float2bfloat16(v.w); lo[3] = __float2bfloat16(v.w - __bfloat162float(hi[3]));
}

// ---------------- fcW split conversion (tiled+swizzled) ----------------
__global__ void wconv_k(const float* __restrict__ fcW)
{
    size_t i = (size_t)blockIdx.x * 256 + threadIdx.x;   // over V_*256 float4s
    if (i >= (size_t)V_ * 256) return;
    int n = (int)(i >> 8), k = (int)(i & 255) * 4;
    float4 v = __ldcg((const float4*)fcW + i);
    __nv_bfloat16 hi[4], lo[4];
    split4(v, hi, lo);
    size_t a = w_big_elem(n, k);
    *(uint64_t*)(g_Wbig + a)        = *(uint64_t*)hi;
    *(uint64_t*)(g_Wbig + a + 8192) = *(uint64_t*)lo;
}

// ---------------- Wih split conversion (tiled+swizzled) ----------------
__global__ void pwconv_k(const float* __restrict__ Wf, const float* __restrict__ Wb,
                         const float* __restrict__ Wd)
{
    size_t i = (size_t)blockIdx.x * 256 + threadIdx.x;   // over 8192*64 float4s
    if (i >= (size_t)8192 * 64) return;
    int row = (int)(i >> 6), k = (int)(i & 63) * 4;
    const float* src; int r = row;
    if (row < 2048)      src = Wf;
    else if (row < 4096) { src = Wb; r = row - 2048; }
    else                 { src = Wd; r = row - 4096; }
    float4 v = __ldcg((const float4*)(src + (size_t)r * E_) + (k >> 2));
    __nv_bfloat16 hi[4], lo[4];
    split4(v, hi, lo);
    size_t a = w_pre_elem(row, k);
    *(uint64_t*)(g_Wp + a)        = *(uint64_t*)hi;
    *(uint64_t*)(g_Wp + a + 8192) = *(uint64_t*)lo;
}

// ---------------- gathered-embedding split conversion (tiled+swizzled) ----------------
__global__ void paconv_k(const float* __restrict__ enc_emb, const float* __restrict__ dec_emb)
{
    size_t i = (size_t)blockIdx.x * 256 + threadIdx.x;   // over 6144*64 float4s
    if (i >= (size_t)6144 * 64) return;
    int row = (int)(i >> 6), k = (int)(i & 63) * 4;
    __nv_bfloat16* base;
    float4 v;
    int m;
    if (row < 4096) {
        v = __ldcg((const float4*)(enc_emb + (size_t)g_enc_rowidx[row] * E_) + (k >> 2));
        base = g_Aenc; m = row;
    } else {
        m = row - 4096;
        base = g_Adec;
        if (m < MROWS)
            v = __ldcg((const float4*)(dec_emb + (size_t)g_dec_rowidx[m] * E_) + (k >> 2));
        else
            v = make_float4(0.f, 0.f, 0.f, 0.f);
    }
    __nv_bfloat16 hi[4], lo[4];
    split4(v, hi, lo);
    size_t a = a_pre_elem(m, k);
    *(uint64_t*)(base + a)         = *(uint64_t*)hi;
    *(uint64_t*)(base + a + 16384) = *(uint64_t*)lo;
}

// ================= shared tcgen05 GEMM plumbing (bulk-copy + SW128) =================
#define STAGE  98304
#define SMEM_HDR 1024
#define SMEM_TC  (SMEM_HDR + 2 * STAGE)
#define IDESC_F16 ((1u<<4)|(1u<<7)|(1u<<10)|((128u/8)<<17)|((128u/16)<<24))

__device__ __forceinline__ uint32_t smem_u32(const void* p)
{
    uint32_t a;
    asm("{ .reg .u64 t; cvta.to.shared.u64 t, %1; cvt.u32.u64 %0, t; }" : "=r"(a) : "l"(p));
    return a;
}

#if HAS_TC
__device__ __forceinline__ uint32_t elect1()
{
    uint32_t p;
    asm volatile("{ .reg .pred p; elect.sync _|p, 0xFFFFFFFF; selp.b32 %0, 1, 0, p; }" : "=r"(p));
    return p;
}
__device__ __forceinline__ void mma_f16_ss(uint32_t d, uint64_t ad, uint64_t bd,
                                           uint32_t idesc, uint32_t en)
{
    asm volatile(
        "{\n\t.reg .pred p;\n\tsetp.ne.u32 p, %5, 0;\n\t"
        "tcgen05.mma.cta_group::1.kind::f16 [%0], %1, %2, %3, {%4,%4,%4,%4}, p;\n\t}"
        :: "r"(d), "l"(ad), "l"(bd), "r"(idesc), "r"(0u), "r"(en) : "memory");
}
__device__ __forceinline__ void bulkcp(uint32_t dst, const void* src, uint32_t bytes,
                                       uint32_t mbar)
{
    asm volatile(
        "cp.async.bulk.shared::cta.global.mbarrier::complete_tx::bytes [%0], [%1], %2, [%3];"
        :: "r"(dst), "l"(src), "r"(bytes), "r"(mbar) : "memory");
}
__device__ __forceinline__ void mbar_wait(uint32_t mbar, uint32_t phase)
{
    uint32_t done;
    do {
        asm volatile(
            "{\n\t.reg .pred q;\n\t"
            "mbarrier.try_wait.parity.shared.b64 q, [%1], %2, 0x989680;\n\t"
            "selp.b32 %0, 1, 0, q;\n\t}"
            : "=r"(done) : "r"(mbar), "r"(phase) : "memory");
    } while (!done);
}

// KCHN chunks; A chunk = 64KB contiguous (32768 elems), W chunk = 32KB (16384 elems).
// Stage layout: [AHI0|AHI1|ALO0|ALO1|WHI|WLO], each 16KB, SW128-swizzled in GLOBAL.
template <int KCHN>
__device__ __forceinline__ uint32_t tc_mainloop(const __nv_bfloat16* Ag,
                                                const __nv_bfloat16* Wg,
                                                uint32_t sbase, int tid, int wid)
{
    if (wid == 0)
        asm volatile("tcgen05.alloc.cta_group::1.sync.aligned.shared::cta.b32 [%0], 512;"
                     :: "r"(sbase) : "memory");
    if (tid == 0) {
        asm volatile("mbarrier.init.shared.b64 [%0], 1;" :: "r"(sbase + 16) : "memory");
        asm volatile("mbarrier.init.shared.b64 [%0], 1;" :: "r"(sbase + 24) : "memory");
        asm volatile("mbarrier.init.shared.b64 [%0], 1;" :: "r"(sbase + 32) : "memory");
        asm volatile("mbarrier.init.shared.b64 [%0], 1;" :: "r"(sbase + 40) : "memory");
    }
    __syncthreads();
    uint32_t tmem;
    asm volatile("ld.shared.b32 %0, [%1];" : "=r"(tmem) : "r"(sbase));

    if (tid == 0) {
#pragma unroll
        for (int c0 = 0; c0 < 2 && c0 < KCHN; c0++) {
            uint32_t lm = sbase + 32 + c0 * 8;
            uint32_t st = sbase + SMEM_HDR + c0 * STAGE;
            asm volatile("mbarrier.arrive.expect_tx.shared.b64 _, [%0], %1;"
                         :: "r"(lm), "r"(98304u) : "memory");
            bulkcp(st,         Ag + (size_t)c0 * 32768, 65536u, lm);
            bulkcp(st + 65536, Wg + (size_t)c0 * 16384, 32768u, lm);
        }
    }

    int lph0 = 0, lph1 = 0, cph0 = 0, cph1 = 0;
    for (int c = 0; c < KCHN; c++) {
        const int p = c & 1;
        mbar_wait(sbase + 32 + p * 8, p ? lph1 : lph0);
        if (p) lph1 ^= 1; else lph0 ^= 1;

        if (wid == 0 && elect1()) {
            const uint32_t st = sbase + SMEM_HDR + p * STAGE;
            // R14-proven SW128 K-major descriptor
            const uint64_t BASE = (uint64_t(2) << 61) | (uint64_t(1) << 46) |
                                  (uint64_t(64) << 32) | (uint64_t(1) << 16);
            uint64_t dAhi0 = BASE | (((st + 0)     >> 4) & 0x3FFF);
            uint64_t dAhi1 = BASE | (((st + 16384) >> 4) & 0x3FFF);
            uint64_t dAlo0 = BASE | (((st + 32768) >> 4) & 0x3FFF);
            uint64_t dAlo1 = BASE | (((st + 49152) >> 4) & 0x3FFF);
            uint64_t dWhi  = BASE | (((st + 65536) >> 4) & 0x3FFF);
            uint64_t dWlo  = BASE | (((st + 81920) >> 4) & 0x3FFF);
#pragma unroll
            for (int ks = 0; ks < 4; ks++) {
                uint32_t en0 = (c == 0 && ks == 0) ? 0u : 1u;
                mma_f16_ss(tmem + 0,   dAhi0 + ks * 2, dWhi + ks * 2, IDESC_F16, en0);
                mma_f16_ss(tmem + 128, dAhi1 + ks * 2, dWhi + ks * 2, IDESC_F16, en0);
                mma_f16_ss(tmem + 0,   dAhi0 + ks * 2, dWlo + ks * 2, IDESC_F16, 1u);
                mma_f16_ss(tmem + 128, dAhi1 + ks * 2, dWlo + ks * 2, IDESC_F16, 1u);
                mma_f16_ss(tmem + 0,   dAlo0 + ks * 2, dWhi + ks * 2, IDESC_F16, 1u);
                mma_f16_ss(tmem + 128, dAlo1 + ks * 2, dWhi + ks * 2, IDESC_F16, 1u);
            }
            asm volatile(
                "tcgen05.commit.cta_group::1.mbarrier::arrive::one.shared::cluster.b64 [%0];"
                :: "r"(sbase + 16 + p * 8) : "memory");
        }
        mbar_wait(sbase + 16 + p * 8, p ? cph1 : cph0);
        if (p) cph1 ^= 1; else cph0 ^= 1;

        if (c + 2 < KCHN && tid == 0) {
            uint32_t lm = sbase + 32 + p * 8;
            uint32_t st = sbase + SMEM_HDR + p * STAGE;
            asm volatile("mbarrier.arrive.expect_tx.shared.b64 _, [%0], %1;"
                         :: "r"(lm), "r"(98304u) : "memory");
            bulkcp(st,         Ag + (size_t)(c + 2) * 32768, 65536u, lm);
            bulkcp(st + 65536, Wg + (size_t)(c + 2) * 16384, 32768u, lm);
        }
    }
    asm volatile("tcgen05.fence::after_thread_sync;" ::: "memory");
    return tmem;
}

#define LDTM32(r, addr) \
    asm volatile( \
        "tcgen05.ld.sync.aligned.32x32b.x32.b32 " \
        "{%0,%1,%2,%3,%4,%5,%6,%7,%8,%9,%10,%11,%12,%13,%14,%15," \
        "%16,%17,%18,%19,%20,%21,%22,%23,%24,%25,%26,%27,%28,%29,%30,%31}, [%32];" \
        : "=r"((r)[0]), "=r"((r)[1]), "=r"((r)[2]), "=r"((r)[3]), "=r"((r)[4]), "=r"((r)[5]), \
          "=r"((r)[6]), "=r"((r)[7]), "=r"((r)[8]), "=r"((r)[9]), "=r"((r)[10]), "=r"((r)[11]), \
          "=r"((r)[12]), "=r"((r)[13]), "=r"((r)[14]), "=r"((r)[15]), "=r"((r)[16]), "=r"((r)[17]), \
          "=r"((r)[18]), "=r"((r)[19]), "=r"((r)[20]), "=r"((r)[21]), "=r"((r)[22]), "=r"((r)[23]), \
          "=r"((r)[24]), "=r"((r)[25]), "=r"((r)[26]), "=r"((r)[27]), "=r"((r)[28]), "=r"((r)[29]), \
          "=r"((r)[30]), "=r"((r)[31]) \
        : "r"(addr))
#endif  // HAS_TC

// ---------------- final logits GEMM ----------------
__global__ __launch_bounds__(256, 1)
void bgemm_tc(const float* __restrict__ bias, float* __restrict__ out)
{
#if HAS_TC
    extern __shared__ __align__(1024) unsigned char sm[];
    const uint32_t sbase = smem_u32(sm);
    const int tid = threadIdx.x, wid = tid >> 5, lane = tid & 31;
    const int n0 = blockIdx.x * 128;
    const int m0g = blockIdx.y * 256;
    const __nv_bfloat16* Ag = g_Abig + (size_t)blockIdx.y * 524288;
    const __nv_bfloat16* Wg = g_Wbig + (size_t)blockIdx.x * 262144;

    uint32_t tmem = tc_mainloop<16>(Ag, Wg, sbase, tid, wid);

    {
        const int sub = tid >> 7;
        const int wiw = (tid >> 5) & 3;
        const int mrow = m0g + sub * 128 + wiw * 32 + lane;
        const uint32_t warp_off = ((uint32_t)(tid & 127) >> 5) << 21;
        const uint32_t dbase = tmem + sub * 128 + warp_off;
        const bool valid = mrow < MROWS;
        const int t = mrow >> 5, b = mrow & 31;
        float* orow = out + (size_t)(b * T_ + t + 1) * V_ + n0;
#pragma unroll
        for (int q = 0; q < 4; q++) {
            uint32_t r[32];
            LDTM32(r, dbase + q * 32);
            asm volatile("tcgen05.wait::ld.sync.aligned;" ::: "memory");
            if (valid) {
#pragma unroll
                for (int c4 = 0; c4 < 8; c4++) {
                    const int n = q * 32 + c4 * 4;
                    float4 bb = *(const float4*)(bias + n0 + n);
                    float4 v;
                    v.x = __uint_as_float(r[c4 * 4 + 0]) + bb.x;
                    v.y = __uint_as_float(r[c4 * 4 + 1]) + bb.y;
                    v.z = __uint_as_float(r[c4 * 4 + 2]) + bb.z;
                    v.w = __uint_as_float(r[c4 * 4 + 3]) + bb.w;
                    *(float4*)(orow + n) = v;
                }
            }
        }
    }
    __syncthreads();
    if (wid == 0) {
        asm volatile("tcgen05.relinquish_alloc_permit.cta_group::1.sync.aligned;" ::: "memory");
        asm volatile("tcgen05.dealloc.cta_group::1.sync.aligned.b32 %0, 512;" :: "r"(tmem));
    }
#endif
}

// ---------------- pregate GEMM (tensor) ----------------
__global__ __launch_bounds__(256, 1)
void pgemm_tc(const __nv_bfloat16* __restrict__ A, const __nv_bfloat16* __restrict__ W,
              const float* __restrict__ bias, float* __restrict__ C,
              int Ntot, int Mvalid)
{
#if HAS_TC
    extern __shared__ __align__(1024) unsigned char sm[];
    const uint32_t sbase = smem_u32(sm);
    const int tid = threadIdx.x, wid = tid >> 5, lane = tid & 31;
    const int n0 = blockIdx.x * 128;
    const int m0g = blockIdx.y * 256;
    const __nv_bfloat16* Ag = A + (size_t)blockIdx.y * 131072;
    const __nv_bfloat16* Wg = W + (size_t)blockIdx.x * 65536;

    uint32_t tmem = tc_mainloop<4>(Ag, Wg, sbase, tid, wid);

    {
        const int sub = tid >> 7;
        const int wiw = (tid >> 5) & 3;
        const int mrow = m0g + sub * 128 + wiw * 32 + lane;
        const uint32_t warp_off = ((uint32_t)(tid & 127) >> 5) << 21;
        const uint32_t dbase = tmem + sub * 128 + warp_off;
        const bool valid = mrow < Mvalid;
        const int t = mrow >> 5, b = mrow & 31;
#pragma unroll
        for (int q = 0; q < 4; q++) {
            uint32_t r[32];
            LDTM32(r, dbase + q * 32);
            asm volatile("tcgen05.wait::ld.sync.aligned;" ::: "memory");
            if (valid) {
#pragma unroll
                for (int c1 = 0; c1 < 32; c1++) {
                    const int n = n0 + q * 32 + c1;
                    C[((size_t)t * Ntot + n) * B_ + b] = __uint_as_float(r[c1]) + bias[n];
                }
            }
        }
    }
    __syncthreads();
    if (wid == 0) {
        asm volatile("tcgen05.relinquish_alloc_permit.cta_group::1.sync.aligned;" ::: "memory");
        asm volatile("tcgen05.dealloc.cta_group::1.sync.aligned.b32 %0, 512;" :: "r"(tmem));
    }
#endif
}

// ---------------- persistent encoder (R10-proven) ----------------
__global__ void enc_persist_k(const float* __restrict__ Whh_f,
                              const float* __restrict__ Whh_b)
{
    extern __shared__ float smemf[];
    float2* sw_if = (float2*)smemf;
    float2* sw_go = (float2*)(smemf + 8192);
    float*  shT   = smemf + 16384;
    const int dir = blockIdx.x >> 6, cb = blockIdx.x & 63;
    const int w = threadIdx.x >> 5, lane = threadIdx.x & 31;
    const int j = cb * 8 + w;
    const float* Whh = dir ? Whh_b : Whh_f;
    const float* preBase = dir ? g_pre_bT : g_pre_fT;
    unsigned* cnt = &g_sync[dir * 64];
    unsigned* gen = &g_sync[dir * 64 + 32];

    {
        const int base_j = cb * 8;
        for (int idx = threadIdx.x; idx < 8 * H_; idx += 256) {
            int c = idx >> 9, k = idx & 511;
            float wi = Whh[(size_t)(0 * H_ + base_j + c) * H_ + k];
            float wf = Whh[(size_t)(1 * H_ + base_j + c) * H_ + k];
            float wg = Whh[(size_t)(2 * H_ + base_j + c) * H_ + k];
            float wo = Whh[(size_t)(3 * H_ + base_j + c) * H_ + k];
            sw_if[idx] = make_float2(wi, wf);
            sw_go[idx] = make_float2(wg, wo);
        }
    }
    __syncthreads();

    const ulonglong2* pif = (const ulonglong2*)(sw_if + (size_t)w * H_);
    const ulonglong2* pgo = (const ulonglong2*)(sw_go + (size_t)w * H_);
    float cst = 0.f;

    for (int s = 0; s < S_; s++) {
        const float4* s4 = (const float4*)g_enc_hT[dir][s & 1];
        float4* d4 = (float4*)shT;
        for (int i = threadIdx.x; i < H_ * B_ / 4; i += 256) d4[i] = __ldcg(s4 + i);
        __syncthreads();
        const int t = dir ? (S_ - 1 - s) : s;
        const float* preT = preBase + (size_t)t * GH * B_;
        unsigned long long acc_if = pk2(__ldcg(preT + (size_t)(0 * H_ + j) * B_ + lane),
                                        __ldcg(preT + (size_t)(1 * H_ + j) * B_ + lane));
        unsigned long long acc_go = pk2(__ldcg(preT + (size_t)(2 * H_ + j) * B_ + lane),
                                        __ldcg(preT + (size_t)(3 * H_ + j) * B_ + lane));
#pragma unroll 4
        for (int k4 = 0; k4 < H_ / 4; k4++) {
            ulonglong2 a01 = pif[k4 * 2], a23 = pif[k4 * 2 + 1];
            ulonglong2 g01 = pgo[k4 * 2], g23 = pgo[k4 * 2 + 1];
            float h0 = shT[(k4 * 4 + 0) * B_ + lane];
            float h1 = shT[(k4 * 4 + 1) * B_ + lane];
            float h2 = shT[(k4 * 4 + 2) * B_ + lane];
            float h3 = shT[(k4 * 4 + 3) * B_ + lane];
            unsigned long long H0 = pk2(h0, h0), H1 = pk2(h1, h1);
            unsigned long long H2 = pk2(h2, h2), H3 = pk2(h3, h3);
            acc_if = ffma2(a01.x, H0, acc_if);
            acc_if = ffma2(a01.y, H1, acc_if);
            acc_if = ffma2(a23.x, H2, acc_if);
            acc_if = ffma2(a23.y, H3, acc_if);
            acc_go = ffma2(g01.x, H0, acc_go);
            acc_go = ffma2(g01.y, H1, acc_go);
            acc_go = ffma2(g23.x, H2, acc_go);
            acc_go = ffma2(g23.y, H3, acc_go);
        }
        float ai, af, ag, ao;
        unpk2(acc_if, ai, af);
        unpk2(acc_go, ag, ao);
        float iv = fsig(ai), fv = fsig(af), gv = ftanh(ag), ov = fsig(ao);
        cst = fv * cst + iv * gv;
        __stcg(&g_enc_hT[dir][(s + 1) & 1][(size_t)j * B_ + lane], ov * ftanh(cst));
        if (s == S_ - 1) g_enc_cT[dir][(size_t)j * B_ + lane] = cst;
        grid_barrier2(cnt, gen, (unsigned)(s + 1), 64u);
    }
}

// ---------------- persistent decoder (R10-proven; tiled+swizzled A emit) ----------------
__global__ void dec_persist_k(const float* __restrict__ Whh)
{
    extern __shared__ float smemf[];
    float2* sw_if = (float2*)smemf;
    float2* sw_go = (float2*)(smemf + 16384);
    float*  shH   = smemf + 32768;
    const int w = threadIdx.x >> 5, lane = threadIdx.x & 31;
    const int j = blockIdx.x * 8 + w;
    unsigned* cnt = &g_sync[128];
    unsigned* gen = &g_sync[160];

    {
        const int base_j = blockIdx.x * 8;
        for (int idx = threadIdx.x; idx < 8 * DH; idx += 256) {
            int c = idx >> 10, k = idx & 1023;
            float wi = Whh[(size_t)(0 * DH + base_j + c) * DH + k];
            float wf = Whh[(size_t)(1 * DH + base_j + c) * DH + k];
            float wg = Whh[(size_t)(2 * DH + base_j + c) * DH + k];
            float wo = Whh[(size_t)(3 * DH + base_j + c) * DH + k];
            sw_if[idx] = make_float2(wi, wf);
            sw_go[idx] = make_float2(wg, wo);
        }
    }

    float cst, h0v;
    if (j < H_) { cst = g_enc_cT[0][j * B_ + lane]; h0v = g_enc_hT[0][0][j * B_ + lane]; }
    else { cst = g_enc_cT[1][(j - H_) * B_ + lane]; h0v = g_enc_hT[1][0][(j - H_) * B_ + lane]; }
    __stcg(&g_dec_hT[0][(size_t)j * B_ + lane], h0v);
    grid_barrier2(cnt, gen, 1u, 128u);

    for (int t = 0; t < TD; t++) {
        const float* preT = g_dec_preT + (size_t)t * DG * B_;
        unsigned long long acc_if = pk2(__ldcg(preT + (size_t)(0 * DH + j) * B_ + lane),
                                        __ldcg(preT + (size_t)(1 * DH + j) * B_ + lane));
        unsigned long long acc_go = pk2(__ldcg(preT + (size_t)(2 * DH + j) * B_ + lane),
                                        __ldcg(preT + (size_t)(3 * DH + j) * B_ + lane));

#pragma unroll
        for (int half = 0; half < 2; half++) {
            const float4* s4 = (const float4*)g_dec_hT[t & 1] + half * 4096;
            float4* d4 = (float4*)shH;
            for (int i = threadIdx.x; i < 4096; i += 256) d4[i] = __ldcg(s4 + i);
            __syncthreads();
            const ulonglong2* pif =
                (const ulonglong2*)(sw_if + (size_t)w * DH) + half * 256;
            const ulonglong2* pgo =
                (const ulonglong2*)(sw_go + (size_t)w * DH) + half * 256;
#pragma unroll 4
            for (int k4 = 0; k4 < 128; k4++) {
                ulonglong2 a01 = pif[k4 * 2], a23 = pif[k4 * 2 + 1];
                ulonglong2 g01 = pgo[k4 * 2], g23 = pgo[k4 * 2 + 1];
                float h0 = shH[(k4 * 4 + 0) * B_ + lane];
                float h1 = shH[(k4 * 4 + 1) * B_ + lane];
                float h2 = shH[(k4 * 4 + 2) * B_ + lane];
                float h3 = shH[(k4 * 4 + 3) * B_ + lane];
                unsigned long long H0 = pk2(h0, h0), H1 = pk2(h1, h1);
                unsigned long long H2 = pk2(h2, h2), H3 = pk2(h3, h3);
                acc_if = ffma2(a01.x, H0, acc_if);
                acc_if = ffma2(a01.y, H1, acc_if);
                acc_if = ffma2(a23.x, H2, acc_if);
                acc_if = ffma2(a23.y, H3, acc_if);
                acc_go = ffma2(g01.x, H0, acc_go);
                acc_go = ffma2(g01.y, H1, acc_go);
                acc_go = ffma2(g23.x, H2, acc_go);
                acc_go = ffma2(g23.y, H3, acc_go);
            }
            if (half == 0) __syncthreads();
        }

        float ai, af, ag, ao;
        unpk2(acc_if, ai, af);
        unpk2(acc_go, ag, ao);
        float iv = fsig(ai), fv = fsig(af), gv = ftanh(ag), ov = fsig(ao);
        cst = fv * cst + iv * gv;
        float hv = ov * ftanh(cst);
        __stcg(&g_dec_hT[(t + 1) & 1][(size_t)j * B_ + lane], hv);
        int m = t * B_ + lane;
        __nv_bfloat16 hi = __float2bfloat16(hv);
        size_t a = a_big_elem(m, j);
        g_Abig[a] = hi;
        g_Abig[a + 16384] = __float2bfloat16(hv - __bfloat162float(hi));
        grid_barrier2(cnt, gen, (unsigned)(t + 2), 128u);
    }
}

// ---------------- launch ----------------
extern "C" void kernel_launch(void* const* d_in, const int* in_sizes, int n_in,
                              void* d_out, int out_size)
{
    (void)in_sizes; (void)n_in; (void)out_size;
    const int*   src     = (const int*)d_in[0];
    const int*   trg     = (const int*)d_in[1];
    const float* enc_emb = (const float*)d_in[2];
    const float* dec_emb = (const float*)d_in[3];
    const float* eWih_f  = (const float*)d_in[4];
    const float* eWhh_f  = (const float*)d_in[5];
    const float* eb_f    = (const float*)d_in[6];
    const float* eWih_b  = (const float*)d_in[7];
    const float* eWhh_b  = (const float*)d_in[8];
    const float* eb_b    = (const float*)d_in[9];
    const float* dWih    = (const float*)d_in[10];
    const float* dWhh    = (const float*)d_in[11];
    const float* db      = (const float*)d_in[12];
    const float* fcW     = (const float*)d_in[13];
    const float* fcb     = (const float*)d_in[14];
    float* out = (float*)d_out;

    cudaFuncSetAttribute(enc_persist_k, cudaFuncAttributeMaxDynamicSharedMemorySize, 131072);
    cudaFuncSetAttribute(dec_persist_k, cudaFuncAttributeMaxDynamicSharedMemorySize, 196608);
    cudaFuncSetAttribute(bgemm_tc, cudaFuncAttributeMaxDynamicSharedMemorySize, SMEM_TC);
    cudaFuncSetAttribute(pgemm_tc, cudaFuncAttributeMaxDynamicSharedMemorySize, SMEM_TC);

    void *p_pre_fT, *p_pre_bT, *p_dec_preT, *p_Wp, *p_Aenc, *p_Adec;
    cudaGetSymbolAddress(&p_pre_fT, g_pre_fT);
    cudaGetSymbolAddress(&p_pre_bT, g_pre_bT);
    cudaGetSymbolAddress(&p_dec_preT, g_dec_preT);
    cudaGetSymbolAddress(&p_Wp, g_Wp);
    cudaGetSymbolAddress(&p_Aenc, g_Aenc);
    cudaGetSymbolAddress(&p_Adec, g_Adec);
    __nv_bfloat16* Wp = (__nv_bfloat16*)p_Wp;

    long total = (long)B_ * V_ + 2L * H_ * B_ + (long)S_ * B_ + (long)TD * B_
               + 192 + (long)(MPAD - MROWS) * 2048;
    prep_k<<<(unsigned)((total + 255) / 256), 256>>>(src, trg, out);
    wconv_k<<<V_, 256>>>(fcW);
    pwconv_k<<<2048, 256>>>(eWih_f, eWih_b, dWih);
    paconv_k<<<1536, 256>>>(enc_emb, dec_emb);

    pgemm_tc<<<dim3(16, 16), 256, SMEM_TC>>>(
        (const __nv_bfloat16*)p_Aenc, Wp, eb_f, (float*)p_pre_fT, GH, 4096);
    pgemm_tc<<<dim3(16, 16), 256, SMEM_TC>>>(
        (const __nv_bfloat16*)p_Aenc, Wp + (size_t)16 * 65536, eb_b, (float*)p_pre_bT, GH, 4096);
    pgemm_tc<<<dim3(32, 8), 256, SMEM_TC>>>(
        (const __nv_bfloat16*)p_Adec, Wp + (size_t)32 * 65536, db, (float*)p_dec_preT, DG, MROWS);

    enc_persist_k<<<128, 256, 131072>>>(eWhh_f, eWhh_b);
    dec_persist_k<<<128, 256, 196608>>>(dWhh);

    bgemm_tc<<<dim3(V_ / 128, MPAD / 256), 256, SMEM_TC>>>(fcb, out);
}